// round 3
// baseline (speedup 1.0000x reference)
#include <cuda_runtime.h>

// ---------------------------------------------------------------------------
// ForceField: V = sum_bonds kb*(|xi-xj|-b0)^2  +  sum_{i<j} eps*(rod^12-2rod^6)
// N = 8192 atoms, B = 8192 bonds.
// Numerics: the result is dominated by the closest pair (rod^12 amplifies d2
// rounding x12), so d2 must replicate the reference GEMM bit-exactly:
//   dot = fma(z,z', fma(y,y', x*x'))  (ascending-k FMA chain, acc from 0)
//   d2  = (sq_i + sq_j) - 2*dot       (x2 exact, one rounded sub)
// ---------------------------------------------------------------------------

constexpr int BI  = 8;     // rows per block tile
constexpr int BJ  = 1024;  // cols per block tile (256 threads * 4)
constexpr int TPB = 256;

#define MAX_VDW_PARTIALS 16384
__device__ float g_vdw_partials[MAX_VDW_PARTIALS];
__device__ float g_bond_partials[64];
__device__ int   g_pairs_is_i64;   // 1 if pairs buffer holds int64 values

// Fast reciprocal: bit-hack seed + 3 Newton steps (FFMA pipe only, no MUFU).
__device__ __forceinline__ float frcp_fast(float v) {
    float y = __int_as_float(0x7EF311C3 - __float_as_int(v));
    y = y * (2.0f - v * y);
    y = y * (2.0f - v * y);
    y = y * (2.0f - v * y);
    return y;
}

// Detect pairs dtype: odd 32-bit words of an int64 index array (values < 2^31)
// are all zero; for int32 data they are random indices. Reads only the first
// n_words32 words (in-bounds under both interpretations).
__global__ void detect_pairs_kernel(const int* __restrict__ p32, int n_words32)
{
    __shared__ int s_or[256];
    int acc = 0;
    for (int k = threadIdx.x * 2 + 1; k < n_words32; k += 2 * 256)
        acc |= p32[k];
    s_or[threadIdx.x] = acc;
    __syncthreads();
    #pragma unroll
    for (int s = 128; s > 0; s >>= 1) {
        if (threadIdx.x < s) s_or[threadIdx.x] |= s_or[threadIdx.x + s];
        __syncthreads();
    }
    if (threadIdx.x == 0) g_pairs_is_i64 = (s_or[0] == 0) ? 1 : 0;
}

__global__ __launch_bounds__(TPB)
void vdw_kernel(const float* __restrict__ x,
                const float* __restrict__ eps,
                const float* __restrict__ rmin,
                int N)
{
    const int i0  = blockIdx.y * BI;
    const int j0  = blockIdx.x * BJ;
    const int tx  = threadIdx.x;
    const int bid = blockIdx.y * gridDim.x + blockIdx.x;

    __shared__ float sxi[BI][3];
    __shared__ float ssq[BI];
    __shared__ float sred[TPB];

    // Entire tile at or below the diagonal: no (i,j) with j>i exists.
    if (j0 + BJ - 1 <= i0) {
        if (tx == 0) g_vdw_partials[bid] = 0.0f;
        return;
    }

    if (tx < BI) {
        int i = i0 + tx;
        float a = 0.f, b = 0.f, c = 0.f;
        if (i < N) { a = x[3*i]; b = x[3*i+1]; c = x[3*i+2]; }
        sxi[tx][0] = a; sxi[tx][1] = b; sxi[tx][2] = c;
        // jnp.sum(x*x,axis=1): rounded mults, left-to-right adds
        ssq[tx] = __fadd_rn(__fadd_rn(__fmul_rn(a,a), __fmul_rn(b,b)), __fmul_rn(c,c));
    }
    __syncthreads();

    const int jb = j0 + tx * 4;
    float acc = 0.0f;

    if (jb + 3 < N) {
        const float4* xp = reinterpret_cast<const float4*>(x + (size_t)jb * 3);
        float4 A = xp[0], Bv = xp[1], C = xp[2];
        float xj[4], yj[4], zj[4], sqj[4];
        xj[0]=A.x;  yj[0]=A.y;  zj[0]=A.z;
        xj[1]=A.w;  yj[1]=Bv.x; zj[1]=Bv.y;
        xj[2]=Bv.z; yj[2]=Bv.w; zj[2]=C.x;
        xj[3]=C.y;  yj[3]=C.z;  zj[3]=C.w;
        #pragma unroll
        for (int e = 0; e < 4; e++)
            sqj[e] = __fadd_rn(__fadd_rn(__fmul_rn(xj[e],xj[e]),
                                         __fmul_rn(yj[e],yj[e])),
                               __fmul_rn(zj[e],zj[e]));

        const bool full = (j0 > i0 + BI - 1);  // tile strictly above diagonal

        if (full) {
            #pragma unroll
            for (int r = 0; r < BI; r++) {
                const int i = i0 + r;
                const float xi = sxi[r][0], yi = sxi[r][1], zi = sxi[r][2];
                const float sqi = ssq[r];
                const size_t row = (size_t)i * N + jb;
                float4 e4 = *reinterpret_cast<const float4*>(eps  + row);
                float4 m4 = *reinterpret_cast<const float4*>(rmin + row);
                float ev[4] = {e4.x, e4.y, e4.z, e4.w};
                float mv[4] = {m4.x, m4.y, m4.z, m4.w};
                #pragma unroll
                for (int e = 0; e < 4; e++) {
                    // GEMM-style ascending-k FMA chain (bit-matches reference)
                    float dot = __fmaf_rn(zi, zj[e],
                                 __fmaf_rn(yi, yj[e], __fmul_rn(xi, xj[e])));
                    float d2  = __fsub_rn(__fadd_rn(sqi, sqj[e]),
                                          __fmul_rn(2.0f, dot));
                    float rc   = frcp_fast(d2);
                    float rm   = mv[e];
                    float rod2 = rm * rm * rc;        // (rmin/dist)^2
                    float r6   = rod2 * rod2 * rod2;
                    float r12  = __fmul_rn(r6, r6);
                    float v    = __fmul_rn(ev[e],
                                  __fsub_rn(r12, __fmul_rn(2.0f, r6)));
                    acc = __fadd_rn(acc, v);
                }
            }
        } else {
            // diagonal-band tile: per-element mask j > i
            #pragma unroll
            for (int r = 0; r < BI; r++) {
                const int i = i0 + r;
                if (i >= N) continue;
                if (jb + 3 <= i) continue;   // all 4 j's <= i: skip loads too
                const float xi = sxi[r][0], yi = sxi[r][1], zi = sxi[r][2];
                const float sqi = ssq[r];
                const size_t row = (size_t)i * N + jb;
                float4 e4 = *reinterpret_cast<const float4*>(eps  + row);
                float4 m4 = *reinterpret_cast<const float4*>(rmin + row);
                float ev[4] = {e4.x, e4.y, e4.z, e4.w};
                float mv[4] = {m4.x, m4.y, m4.z, m4.w};
                #pragma unroll
                for (int e = 0; e < 4; e++) {
                    const bool valid = (jb + e) > i;
                    float dot = __fmaf_rn(zi, zj[e],
                                 __fmaf_rn(yi, yj[e], __fmul_rn(xi, xj[e])));
                    float d2  = __fsub_rn(__fadd_rn(sqi, sqj[e]),
                                          __fmul_rn(2.0f, dot));
                    d2 = valid ? d2 : 1.0f;          // keep rcp finite on diag
                    float eh = valid ? ev[e] : 0.0f;
                    float rc   = frcp_fast(d2);
                    float rm   = mv[e];
                    float rod2 = rm * rm * rc;
                    float r6   = rod2 * rod2 * rod2;
                    float r12  = __fmul_rn(r6, r6);
                    float v    = __fmul_rn(eh,
                                  __fsub_rn(r12, __fmul_rn(2.0f, r6)));
                    acc = __fadd_rn(acc, v);
                }
            }
        }
    }

    sred[tx] = acc;
    __syncthreads();
    #pragma unroll
    for (int s = TPB / 2; s > 0; s >>= 1) {
        if (tx < s) sred[tx] += sred[tx + s];
        __syncthreads();
    }
    if (tx == 0) g_vdw_partials[bid] = sred[0];
}

__global__ __launch_bounds__(TPB)
void bond_kernel(const float* __restrict__ x,
                 const void* __restrict__ pairs_raw,
                 const float* __restrict__ kb,
                 const float* __restrict__ b0,
                 int Bn, int N)
{
    __shared__ float sred[TPB];
    int t = blockIdx.x * blockDim.x + threadIdx.x;
    float v = 0.0f;
    if (t < Bn) {
        int i, j;
        if (g_pairs_is_i64) {
            const long long* p = (const long long*)pairs_raw;
            i = (int)p[2 * t]; j = (int)p[2 * t + 1];
        } else {
            const int* p = (const int*)pairs_raw;
            i = p[2 * t]; j = p[2 * t + 1];
        }
        i = min(max(i, 0), N - 1);
        j = min(max(j, 0), N - 1);
        float dx = __fsub_rn(x[3*i],   x[3*j]);
        float dy = __fsub_rn(x[3*i+1], x[3*j+1]);
        float dz = __fsub_rn(x[3*i+2], x[3*j+2]);
        float d2 = __fadd_rn(__fadd_rn(__fmul_rn(dx,dx), __fmul_rn(dy,dy)),
                             __fmul_rn(dz,dz));
        float dis = sqrtf(d2);
        float df  = __fsub_rn(dis, b0[t]);
        v = __fmul_rn(kb[t], __fmul_rn(df, df));
    }
    sred[threadIdx.x] = v;
    __syncthreads();
    #pragma unroll
    for (int s = TPB / 2; s > 0; s >>= 1) {
        if (threadIdx.x < s) sred[threadIdx.x] += sred[threadIdx.x + s];
        __syncthreads();
    }
    if (threadIdx.x == 0) g_bond_partials[blockIdx.x] = sred[0];
}

__global__ __launch_bounds__(256)
void reduce_kernel(float* __restrict__ out, int nV, int nB)
{
    __shared__ double sd[256];
    double s = 0.0;
    for (int k = threadIdx.x; k < nV; k += 256) s += (double)g_vdw_partials[k];
    for (int k = threadIdx.x; k < nB; k += 256) s += (double)g_bond_partials[k];
    sd[threadIdx.x] = s;
    __syncthreads();
    #pragma unroll
    for (int st = 128; st > 0; st >>= 1) {
        if (threadIdx.x < st) sd[threadIdx.x] += sd[threadIdx.x + st];
        __syncthreads();
    }
    if (threadIdx.x == 0) out[0] = (float)sd[0];
}

extern "C" void kernel_launch(void* const* d_in, const int* in_sizes, int n_in,
                              void* d_out, int out_size)
{
    const float* x     = (const float*)d_in[0];
    const void*  pairs = d_in[1];
    const float* kb    = (const float*)d_in[2];
    const float* b0    = (const float*)d_in[3];
    const float* eps   = (const float*)d_in[4];
    const float* rmin  = (const float*)d_in[5];

    const int N  = in_sizes[0] / 3;   // 8192
    const int Bn = in_sizes[2];       // 8192

    detect_pairs_kernel<<<1, 256>>>((const int*)pairs, in_sizes[1]);

    dim3 grid((N + BJ - 1) / BJ, (N + BI - 1) / BI);
    vdw_kernel<<<grid, TPB>>>(x, eps, rmin, N);

    int gb = (Bn + TPB - 1) / TPB;
    bond_kernel<<<gb, TPB>>>(x, pairs, kb, b0, Bn, N);

    reduce_kernel<<<1, 256>>>((float*)d_out, grid.x * grid.y, gb);
}